// round 8
// baseline (speedup 1.0000x reference)
#include <cuda_runtime.h>
#include <cuda_bf16.h>

// Triplet margin loss, D=4096 fp32, B=24576 rows -> 8192 triplets.
// Pure HBM-streaming problem: read 402.7 MB once, emit one scalar.
//
// Persistent single-wave kernel. grid = 148 SMs x 8 CTAs = 1184 CTAs
// (one full wave at 256thr/32reg occupancy); each CTA grid-strides over ~7
// triplets. Removes the 6.92-wave quantization + per-wave-transition cost
// that held the previous version at 80% DRAM. Last-CTA finalize as before.

#define MARGIN 1.0f
#define D_DIM  4096
#define D4     (D_DIM / 4)   // 1024 float4 per row
#define NTHREADS 256
#define GRID_CTAS (148 * 8)  // one full wave on B200

__device__ float        g_loss_sum  = 0.0f;
__device__ unsigned int g_done_ctas = 0u;

__global__ __launch_bounds__(NTHREADS, 8) void tl_persist_kernel(
    const float4* __restrict__ x, float* __restrict__ out,
    int triplets, float inv_triplets)
{
    const int lane = threadIdx.x & 31;
    const int wid  = threadIdx.x >> 5;

    __shared__ float s_qp[NTHREADS / 32];
    __shared__ float s_qn[NTHREADS / 32];

    float hinge_acc = 0.0f;   // meaningful on thread 0 only

    for (int t = blockIdx.x; t < triplets; t += gridDim.x) {
        const float4* __restrict__ q = x + (size_t)t * 3 * D4;
        const float4* __restrict__ p = q + D4;
        const float4* __restrict__ n = p + D4;

        float sqp = 0.0f;   // sum (q-p)^2
        float sqn = 0.0f;   // sum (q-n)^2

        // 1024 float4 / 256 threads = 4 iterations, fully unrolled so ptxas
        // front-batches 12 independent LDG.128s (MLP hides DRAM latency).
        #pragma unroll
        for (int it = 0; it < D4 / NTHREADS; ++it) {
            const int i = it * NTHREADS + threadIdx.x;
            const float4 qa = q[i];
            const float4 pa = p[i];
            const float4 na = n[i];
            float d;
            d = qa.x - pa.x; sqp = fmaf(d, d, sqp);
            d = qa.y - pa.y; sqp = fmaf(d, d, sqp);
            d = qa.z - pa.z; sqp = fmaf(d, d, sqp);
            d = qa.w - pa.w; sqp = fmaf(d, d, sqp);
            d = qa.x - na.x; sqn = fmaf(d, d, sqn);
            d = qa.y - na.y; sqn = fmaf(d, d, sqn);
            d = qa.z - na.z; sqn = fmaf(d, d, sqn);
            d = qa.w - na.w; sqn = fmaf(d, d, sqn);
        }

        // Warp reduction of the pair
        #pragma unroll
        for (int off = 16; off > 0; off >>= 1) {
            sqp += __shfl_down_sync(0xFFFFFFFFu, sqp, off);
            sqn += __shfl_down_sync(0xFFFFFFFFu, sqn, off);
        }
        if (lane == 0) { s_qp[wid] = sqp; s_qn[wid] = sqn; }
        __syncthreads();

        if (threadIdx.x == 0) {
            float a = 0.0f, b = 0.0f;
            #pragma unroll
            for (int w = 0; w < NTHREADS / 32; ++w) { a += s_qp[w]; b += s_qn[w]; }
            const float hinge = MARGIN + sqrtf(a) - sqrtf(b);
            if (hinge > 0.0f) hinge_acc += hinge;
        }
        __syncthreads();   // protect s_qp/s_qn reuse next iteration
    }

    if (threadIdx.x == 0) {
        if (hinge_acc != 0.0f) atomicAdd(&g_loss_sum, hinge_acc);

        // Make this CTA's contribution globally visible, then arrive.
        __threadfence();
        const unsigned int old = atomicAdd(&g_done_ctas, 1u);
        if (old == gridDim.x - 1u) {
            // Last CTA: all adds visible (fence-before-arrive on every CTA).
            const float s = atomicAdd(&g_loss_sum, 0.0f);
            out[0] = fmaxf(s * inv_triplets, 0.0f);
            // Reset state for the next graph replay (atomics -> L2-resident).
            atomicExch(&g_loss_sum, 0.0f);
            __threadfence();
            atomicExch(&g_done_ctas, 0u);
        }
    }
}

extern "C" void kernel_launch(void* const* d_in, const int* in_sizes, int n_in,
                              void* d_out, int out_size) {
    const float4* x = (const float4*)d_in[0];
    float* out = (float*)d_out;

    const long long total = in_sizes[0];         // B * D
    const int triplets = (int)(total / (3LL * D_DIM));

    const int grid = (triplets < GRID_CTAS) ? triplets : GRID_CTAS;
    tl_persist_kernel<<<grid, NTHREADS>>>(x, out, triplets, 1.0f / (float)triplets);
}